// round 17
// baseline (speedup 1.0000x reference)
#include <cuda_runtime.h>
#include <cuda_bf16.h>
#include <cuda_fp16.h>
#include <cstdint>

// Problem constants
#define BB 2
#define NN 65536
#define CC 256
#define HH 8
#define DD 64
#define SS 64
#define INNERD 512
#define NTOK (BB * NN)      // 131072
#define NCTA (NTOK / 128)   // 1024

// smem byte offsets. Row strides: A=528B, B/w/f=272B (==4 mod 32 words, ldmatrix-safe)
#define ABR 528
#define BBR 272
#define A0B 0                          // A: 128 x 528 = 67584
#define BSB 67584                      // B slab: 128 x 272 = 34816
#define W0B BSB                        // w aliases slab (64 x 272)
#define F0B (BSB + 64 * BBR)           // 84992
#define BIASS (BSB + 34816)            // 102400: beff[64] f32
#define BIASD (BIASS + 256)
#define SMEM_TOTAL (BIASD + 256)       // 102912 bytes -> 2 CTAs/SM

// Device scratch
__device__ __align__(16) float g_Weff[HH][CC][SS];
__device__ __align__(16) float g_beff[HH][SS];
__device__ __align__(16) float g_acc[BB * HH * SS * DD];
__device__ __align__(16) float g_norm[BB * HH * SS];
__device__ __align__(16) uint32_t g_Bh[HH * 128 * 128];  // fp16x2 B^T images

// ---------------- helpers ----------------
__device__ __forceinline__ uint32_t smem_u32(const void* p) {
    uint32_t a;
    asm("{ .reg .u64 t; cvta.to.shared.u64 t, %1; cvt.u32.u64 %0, t; }" : "=r"(a) : "l"(p));
    return a;
}
__device__ __forceinline__ void ldsm4(uint32_t* r, uint32_t addr) {
    asm volatile("ldmatrix.sync.aligned.m8n8.x4.shared.b16 {%0,%1,%2,%3}, [%4];"
                 : "=r"(r[0]), "=r"(r[1]), "=r"(r[2]), "=r"(r[3]) : "r"(addr));
}
__device__ __forceinline__ void mma_f16(float* c, uint32_t a0, uint32_t a1,
                                        uint32_t a2, uint32_t a3,
                                        uint32_t b0, uint32_t b1) {
    asm volatile(
        "mma.sync.aligned.m16n8k16.row.col.f32.f16.f16.f32 "
        "{%0,%1,%2,%3}, {%4,%5,%6,%7}, {%8,%9}, {%0,%1,%2,%3};"
        : "+f"(c[0]), "+f"(c[1]), "+f"(c[2]), "+f"(c[3])
        : "r"(a0), "r"(a1), "r"(a2), "r"(a3), "r"(b0), "r"(b1));
}
__device__ __forceinline__ uint32_t pack2(float lo, float hi) {
    __half2 h = __floats2half2_rn(lo, hi);
    return *reinterpret_cast<uint32_t*>(&h);
}

// ---------------------------------------------------------------- zero
__global__ void zero_kernel() {
    int i = blockIdx.x * blockDim.x + threadIdx.x;
    if (i < BB * HH * SS * DD) g_acc[i] = 0.0f;
    if (i < BB * HH * SS)      g_norm[i] = 0.0f;
}

// ------------------------------------------------- precompute Weff/beff
__global__ void precompute_kernel(const float* __restrict__ Wx,
                                  const float* __restrict__ bx,
                                  const float* __restrict__ Wslice,
                                  const float* __restrict__ bslice) {
    int m = blockIdx.x;
    int s = threadIdx.x;
    if (m < HH * CC) {
        int h = m / CC, k = m % CC;
        float a = 0.0f;
#pragma unroll 16
        for (int d = 0; d < DD; d++)
            a += Wx[(size_t)k * INNERD + h * DD + d] * Wslice[d * SS + s];
        g_Weff[h][k][s] = a;
    } else {
        for (int h = 0; h < HH; h++) {
            float a = bslice[s];
            for (int d = 0; d < DD; d++)
                a += bx[h * DD + d] * Wslice[d * SS + s];
            g_beff[h][s] = a;
        }
    }
}

// ---- B^T images [h][n(64 s | 64 d)][128 u32], fp16 pairs
__global__ void build_bt(const float* __restrict__ Wfx) {
    int h = blockIdx.x;
    for (int i = threadIdx.x; i < 128 * 128; i += 256) {
        int n = i >> 7, c = i & 127;
        float v0, v1;
        if (n < 64) {
            v0 = g_Weff[h][2 * c][n];
            v1 = g_Weff[h][2 * c + 1][n];
        } else {
            v0 = Wfx[(size_t)(2 * c)     * INNERD + h * DD + (n - 64)];
            v1 = Wfx[(size_t)(2 * c + 1) * INNERD + h * DD + (n - 64)];
        }
        g_Bh[(h * 128 + n) * 128 + c] = pack2(v0, v1);
    }
}

// ---------------------------------------------------------------- main
extern __shared__ unsigned char smem[];

__global__ __launch_bounds__(128, 2) void fused_main(
    const float* __restrict__ x,
    const float* __restrict__ bfx,
    const float* __restrict__ temperature)
{
    const uint32_t smb = smem_u32(smem);
    const int t    = threadIdx.x;
    const int wp   = t >> 5;          // 0..3
    const int lane = t & 31;
    const int g    = lane >> 2;
    const int q    = lane & 3;
    const int wm   = wp & 1;          // m-group (64 tok)
    const int wn   = wp >> 1;         // 0: s-half, 1: d-half
    const int ct   = blockIdx.x;
    const int tok0 = ct * 128;
    const int b    = ct >> 9;

    uint32_t* smu = (uint32_t*)smem;
    float*    smf = (float*)smem;

    // ldmatrix lane-address components
    const int a_row  = (lane & 7) + ((lane >> 3) & 1) * 8;
    const int a_k16b = (lane >> 4) * 16;
    const int b_row  = (lane & 7) + (lane >> 4) * 8;
    const int b_k16b = ((lane >> 3) & 1) * 16;

    // ---- stage A once: fp16 pairs ----
    for (int it = 0; it < 64; it++) {
        int idx = it * 128 + t;               // 128 rows x 64 float4
        int row = idx >> 6, j = idx & 63;
        float4 v = *(const float4*)&x[((size_t)(tok0 + row)) * CC + j * 4];
        uint2 pv;
        pv.x = pack2(v.x, v.y);
        pv.y = pack2(v.z, v.w);
        *(uint2*)&smu[(A0B / 4) + row * 132 + 2 * j] = pv;
    }

    // hoisted ldmatrix base addresses
    const uint32_t aBase = smb + A0B + (wm * 64 + a_row) * ABR + a_k16b;   // +mt*16*ABR +kk*32
    const uint32_t bBase = smb + BSB + (wn * 64 + b_row) * BBR + b_k16b;   // +np*16*BBR +ks*32
    const uint32_t wBase = smb + W0B + ((wp & 1) * 32 + a_row) * BBR + a_k16b;
    const uint32_t fBase = smb + F0B + ((wp >> 1) * 32 + b_row) * BBR + b_k16b;

    for (int h = 0; h < HH; h++) {
        __syncthreads();   // prior head's w/f reads done -> slab/bias writable
        if (t < 64) {
            smf[BIASS / 4 + t] = g_beff[h][t];
            smf[BIASD / 4 + t] = bfx[h * DD + t];
        }
        float tmp = temperature[h];
        tmp = fminf(fmaxf(tmp, 0.5f), 5.0f);
        const float invt = __fdividef(1.0f, tmp);

        float c[4][8][4];      // mt(16-row) x nt(8-col) x frag
#pragma unroll
        for (int i = 0; i < 4; i++)
#pragma unroll
            for (int j = 0; j < 8; j++)
#pragma unroll
                for (int e = 0; e < 4; e++) c[i][j][e] = 0.0f;

        const uint32_t* img = g_Bh + (size_t)h * 128 * 128;

        // ============ GEMM1: m64n64/warp, two K-halves of 128 ============
#pragma unroll
        for (int kh = 0; kh < 2; kh++) {
            if (kh) __syncthreads();
            // stage B slab [128 n][64 u32]
#pragma unroll
            for (int it = 0; it < 16; it++) {
                int idx = it * 128 + t;       // 128 rows x 16 uint4
                int row = idx >> 4, c4 = idx & 15;
                uint4 v = *(const uint4*)&img[(size_t)row * 128 + kh * 64 + c4 * 4];
                *(uint4*)&smu[(BSB / 4) + row * 68 + c4 * 4] = v;
            }
            __syncthreads();

#pragma unroll
            for (int ks = 0; ks < 8; ks++) {
                const int akk = (kh * 8 + ks) * 32;
                uint32_t a[4][4];
#pragma unroll
                for (int mt = 0; mt < 4; mt++)
                    ldsm4(a[mt], aBase + mt * 16 * ABR + akk);
#pragma unroll
                for (int np = 0; np < 4; np++) {
                    uint32_t bh[4];
                    ldsm4(bh, bBase + np * 16 * BBR + ks * 32);
#pragma unroll
                    for (int mt = 0; mt < 4; mt++) {
                        mma_f16(c[mt][np * 2],     a[mt][0], a[mt][1], a[mt][2], a[mt][3],
                                bh[0], bh[1]);
                        mma_f16(c[mt][np * 2 + 1], a[mt][0], a[mt][1], a[mt][2], a[mt][3],
                                bh[2], bh[3]);
                    }
                }
            }
        }
        __syncthreads();   // slab reads done -> w/f stores may overwrite

        // ============ softmax (s-half warps) / bias+store (d-half warps) ============
        float nacc[16];
#pragma unroll
        for (int i = 0; i < 16; i++) nacc[i] = 0.0f;

        if (wn == 0) {
            const float* bs = &smf[BIASS / 4];
#pragma unroll
            for (int mt = 0; mt < 4; mt++)
#pragma unroll
                for (int rr = 0; rr < 2; rr++) {
                    const int tok = wm * 64 + mt * 16 + g + 8 * rr;
                    float pv[16];
                    float mx = -1e30f;
#pragma unroll
                    for (int nt = 0; nt < 8; nt++)
#pragma unroll
                        for (int e = 0; e < 2; e++) {
                            float p = (c[mt][nt][rr * 2 + e] + bs[nt * 8 + 2 * q + e]) * invt;
                            pv[nt * 2 + e] = p;
                            mx = fmaxf(mx, p);
                        }
                    mx = fmaxf(mx, __shfl_xor_sync(0xffffffffu, mx, 1));
                    mx = fmaxf(mx, __shfl_xor_sync(0xffffffffu, mx, 2));
                    float sv = 0.0f;
#pragma unroll
                    for (int j = 0; j < 16; j++) { pv[j] = __expf(pv[j] - mx); sv += pv[j]; }
                    sv += __shfl_xor_sync(0xffffffffu, sv, 1);
                    sv += __shfl_xor_sync(0xffffffffu, sv, 2);
                    const float r = __fdividef(1.0f, sv);
#pragma unroll
                    for (int nt = 0; nt < 8; nt++)
#pragma unroll
                        for (int e = 0; e < 2; e++) {
                            float wv = pv[nt * 2 + e] * r;
                            nacc[nt * 2 + e] += wv;
                            int s = nt * 8 + 2 * q + e;
                            *(__half*)(smem + W0B + s * BBR + tok * 2) = __float2half_rn(wv);
                        }
                }
        } else {
            const float* bd = &smf[BIASD / 4];
#pragma unroll
            for (int mt = 0; mt < 4; mt++)
#pragma unroll
                for (int rr = 0; rr < 2; rr++) {
                    const int tok = wm * 64 + mt * 16 + g + 8 * rr;
#pragma unroll
                    for (int nt = 0; nt < 8; nt++)
#pragma unroll
                        for (int e = 0; e < 2; e++) {
                            int d = nt * 8 + 2 * q + e;
                            *(__half*)(smem + F0B + d * BBR + tok * 2) =
                                __float2half_rn(c[mt][nt][rr * 2 + e] + bd[d]);
                        }
                }
        }
        __syncthreads();

        // ============ rank update: acc[64 s][64 d] += w^T @ fx (s32 x d32 per warp) ============
        {
            float racc[2][4][4];
#pragma unroll
            for (int i = 0; i < 2; i++)
#pragma unroll
                for (int j = 0; j < 4; j++)
#pragma unroll
                    for (int e = 0; e < 4; e++) racc[i][j][e] = 0.0f;

#pragma unroll
            for (int ks = 0; ks < 8; ks++) {
                uint32_t aw[2][4], bh[8];
                ldsm4(aw[0], wBase + ks * 32);
                ldsm4(aw[1], wBase + 16 * BBR + ks * 32);
                ldsm4(&bh[0], fBase + ks * 32);
                ldsm4(&bh[4], fBase + 16 * BBR + ks * 32);
#pragma unroll
                for (int mt = 0; mt < 2; mt++)
#pragma unroll
                    for (int nt = 0; nt < 4; nt++)
                        mma_f16(racc[mt][nt], aw[mt][0], aw[mt][1], aw[mt][2], aw[mt][3],
                                bh[nt * 2], bh[nt * 2 + 1]);
            }

            const int abase = (b * HH + h) * SS;
            const int wm2 = wp & 1, wn2 = wp >> 1;
#pragma unroll
            for (int mt = 0; mt < 2; mt++)
#pragma unroll
                for (int nt = 0; nt < 4; nt++)
#pragma unroll
                    for (int rr = 0; rr < 2; rr++)
#pragma unroll
                        for (int e = 0; e < 2; e++) {
                            int s = wm2 * 32 + mt * 16 + g + 8 * rr;
                            int d = wn2 * 32 + nt * 8 + 2 * q + e;
                            atomicAdd(&g_acc[(abase + s) * DD + d],
                                      racc[mt][nt][rr * 2 + e]);
                        }
        }

        // ---- norm reduce + atomics (s-half warps) ----
        if (wn == 0) {
#pragma unroll
            for (int j = 0; j < 16; j++) {
                nacc[j] += __shfl_xor_sync(0xffffffffu, nacc[j], 4);
                nacc[j] += __shfl_xor_sync(0xffffffffu, nacc[j], 8);
                nacc[j] += __shfl_xor_sync(0xffffffffu, nacc[j], 16);
            }
            if (g == 0) {
                const int nb = (b * HH + h) * SS;
#pragma unroll
                for (int nt = 0; nt < 8; nt++)
#pragma unroll
                    for (int e = 0; e < 2; e++)
                        atomicAdd(&g_norm[nb + nt * 8 + 2 * q + e], nacc[nt * 2 + e]);
            }
        }
    }
}

// ------------------------------------------------------------ finalize
__global__ void finalize_kernel(float* __restrict__ out) {
    int i = blockIdx.x * blockDim.x + threadIdx.x;
    if (i < BB * HH * SS * DD)
        out[i] = g_acc[i] / (g_norm[i >> 6] + 0.01f);
}

// -------------------------------------------------------------- launch
extern "C" void kernel_launch(void* const* d_in, const int* in_sizes, int n_in,
                              void* d_out, int out_size) {
    const float* x           = (const float*)d_in[0];
    const float* Wx          = (const float*)d_in[1];
    const float* bx          = (const float*)d_in[2];
    const float* Wfx         = (const float*)d_in[3];
    const float* bfx         = (const float*)d_in[4];
    const float* Wslice      = (const float*)d_in[5];
    const float* bslice      = (const float*)d_in[6];
    const float* temperature = (const float*)d_in[7];
    float* out = (float*)d_out;

    cudaFuncSetAttribute(fused_main, cudaFuncAttributeMaxDynamicSharedMemorySize,
                         SMEM_TOTAL);

    zero_kernel<<<(BB * HH * SS * DD + 255) / 256, 256>>>();
    precompute_kernel<<<HH * CC + 1, 64>>>(Wx, bx, Wslice, bslice);
    build_bt<<<HH, 256>>>(Wfx);
    fused_main<<<NCTA, 128, SMEM_TOTAL>>>(x, bfx, temperature);
    finalize_kernel<<<(BB * HH * SS * DD + 255) / 256, 256>>>(out);
}